// round 3
// baseline (speedup 1.0000x reference)
#include <cuda_runtime.h>
#include <cstdint>

#define NMP     3
#define NNODES  50000
#define D       128
#define E       32
#define DEG     32
#define NEDGE   200000
#define BB      1024
#define S       16
#define NC      8
#define M1      (BB*S)      /* 16384 */
#define DE      (D+E)       /* 160 */

// ---------------- scratch (static device globals; no runtime alloc) ----------------
__device__ int   g_nb1 [NMP*M1];
__device__ int   g_eid1[NMP*M1];
__device__ float g_nin2[(size_t)NMP*M1*DE];   // hop-2 mean [3,16384,160]
__device__ float g_nin1[NMP*BB*DE];           // hop-1 mean [3,1024,160]
__device__ float g_h1  [(size_t)NMP*M1*D];    // layer0 feats at hop-1 [3,16384,128]
__device__ float g_h0  [NMP*BB*D];            // layer0 feats at root  [3,1024,128]
__device__ float g_ninL1[NMP*BB*DE];          // layer1 mean [3,1024,160] (written by GEMM epilogues)
__device__ float g_outs[NMP*BB*D];            // per-metapath embedding [3,1024,128]

// ---------------- helpers ----------------
__device__ __forceinline__ float tf32r(float x) {
    uint32_t u; asm("cvt.rna.tf32.f32 %0, %1;" : "=r"(u) : "f"(x));
    return __uint_as_float(u);
}
__device__ __forceinline__ uint32_t fu(float x) { return __float_as_uint(x); }
__device__ __forceinline__ float4 t4(float4 v) {
    return make_float4(tf32r(v.x), tf32r(v.y), tf32r(v.z), tf32r(v.w));
}
__device__ __forceinline__ uint32_t sptr(const void* p) {
    return (uint32_t)__cvta_generic_to_shared(p);
}
__device__ __forceinline__ void ldsm_x4(uint32_t& d0, uint32_t& d1, uint32_t& d2, uint32_t& d3,
                                        uint32_t a) {
    asm volatile("ldmatrix.sync.aligned.m8n8.x4.shared.b16 {%0,%1,%2,%3}, [%4];"
        : "=r"(d0), "=r"(d1), "=r"(d2), "=r"(d3) : "r"(a));
}

#define MMA_TF32(c, a, b) \
    asm volatile("mma.sync.aligned.m16n8k8.row.col.f32.tf32.tf32.f32 " \
        "{%0,%1,%2,%3}, {%4,%5,%6,%7}, {%8,%9}, {%0,%1,%2,%3};" \
        : "+f"((c)[0]), "+f"((c)[1]), "+f"((c)[2]), "+f"((c)[3]) \
        : "r"((a)[0]), "r"((a)[1]), "r"((a)[2]), "r"((a)[3]), \
          "r"((b)[0]), "r"((b)[1]))

// ---------------- 1) hop-1 neighbor / edge ids ----------------
__global__ void k_idx(const int* __restrict__ ids,
                      const int* __restrict__ adj_nodes,
                      const int* __restrict__ adj_edges) {
    int t = blockIdx.x * blockDim.x + threadIdx.x;
    if (t >= NMP * M1) return;
    int mp = t / M1;
    int r  = t % M1;
    int b  = r >> 4;
    int s  = r & 15;
    long base = ((long)mp * NNODES + ids[b]) * DEG + s;
    g_nb1[t]  = adj_nodes[base];
    g_eid1[t] = adj_edges[base];
}

// ---------------- 2) hop-2 gather + mean -> nin2 ----------------
__global__ void k_mean_hop2(const float* __restrict__ feats,
                            const float* __restrict__ edge_emb,
                            const int* __restrict__ adj_nodes,
                            const int* __restrict__ adj_edges) {
    int w    = (blockIdx.x * blockDim.x + threadIdx.x) >> 5;
    int lane = threadIdx.x & 31;
    if (w >= NMP * M1) return;
    int mp = w / M1;
    long abase = ((long)mp * NNODES + g_nb1[w]) * DEG;
    const int* an = adj_nodes + abase;
    const int* ae = adj_edges + abase;
    float4 aF = make_float4(0.f,0.f,0.f,0.f);
    float4 aE = make_float4(0.f,0.f,0.f,0.f);
    #pragma unroll
    for (int s = 0; s < S; s++) {
        int nb = an[s];
        float4 v = ((const float4*)(feats + (long)nb * D))[lane];
        aF.x += v.x; aF.y += v.y; aF.z += v.z; aF.w += v.w;
        if (lane < E/4) {
            int e = ae[s];
            float4 u = ((const float4*)(edge_emb + ((long)mp * NEDGE + e) * E))[lane];
            aE.x += u.x; aE.y += u.y; aE.z += u.z; aE.w += u.w;
        }
    }
    const float inv = 1.0f / S;
    float4* o = (float4*)(g_nin2 + (size_t)w * DE);
    o[lane] = make_float4(aF.x*inv, aF.y*inv, aF.z*inv, aF.w*inv);
    if (lane < E/4)
        o[D/4 + lane] = make_float4(aE.x*inv, aE.y*inv, aE.z*inv, aE.w*inv);
}

// ---------------- 3) hop-1 gather + mean -> nin1 ----------------
__global__ void k_mean_hop1(const float* __restrict__ feats,
                            const float* __restrict__ edge_emb) {
    int w    = (blockIdx.x * blockDim.x + threadIdx.x) >> 5;
    int lane = threadIdx.x & 31;
    if (w >= NMP * BB) return;
    int mp = w / BB;
    int b  = w % BB;
    int base = mp * M1 + b * S;
    float4 aF = make_float4(0.f,0.f,0.f,0.f);
    float4 aE = make_float4(0.f,0.f,0.f,0.f);
    #pragma unroll
    for (int s = 0; s < S; s++) {
        int nb = g_nb1[base + s];
        float4 v = ((const float4*)(feats + (long)nb * D))[lane];
        aF.x += v.x; aF.y += v.y; aF.z += v.z; aF.w += v.w;
        if (lane < E/4) {
            int e = g_eid1[base + s];
            float4 u = ((const float4*)(edge_emb + ((long)mp * NEDGE + e) * E))[lane];
            aE.x += u.x; aE.y += u.y; aE.z += u.z; aE.w += u.w;
        }
    }
    const float inv = 1.0f / S;
    float4* o = (float4*)(g_nin1 + (size_t)w * DE);
    o[lane] = make_float4(aF.x*inv, aF.y*inv, aF.z*inv, aF.w*inv);
    if (lane < E/4)
        o[D/4 + lane] = make_float4(aE.x*inv, aE.y*inv, aE.z*inv, aE.w*inv);
}

// ---------------- node GEMM (TF32 tensor core, ldmatrix fragments) ----------------
// out = relu(P1row @ Wself + P2row @ Wneigh), K = 288
// MODE 0: h1  (M=16384) + fused 16-row mean -> g_ninL1[:, :D]
// MODE 1: h0  (M=1024)
// MODE 2: outs(M=1024)
template<int MODE>
__global__ __launch_bounds__(256) void gemm_h(const float* __restrict__ feats,
                                              const int*   __restrict__ ids,
                                              const float* __restrict__ W_self,
                                              const float* __restrict__ W_neigh,
                                              int l) {
    constexpr int M    = (MODE == 0) ? M1 : BB;
    constexpr int KTOT = D + DE;          // 288
    constexpr int NSTG = KTOT / 16;       // 18
    int mp = blockIdx.y;
    int m0 = blockIdx.x * 128;

    __shared__ float As[2][128][20];
    __shared__ float Bs[2][16][136];
    __shared__ const float* rowp[128];

    int tid  = threadIdx.x;
    int lane = tid & 31;
    int w    = tid >> 5;
    int wm   = w >> 2;          // 0..1 (rows 64*wm)
    int wn   = w & 3;           // 0..3 (cols 32*wn)
    int ar   = tid >> 1;        // A ld row 0..127
    int kq   = (tid & 1) * 8;   // A ld k offset 0/8
    int bk   = tid >> 4;        // B ld k row
    int bn   = (tid & 15) * 8;  // B ld n offset
    int row16 = lane & 15;
    int sel4  = (lane >> 4) * 4;
    uint32_t lmoff = (uint32_t)((row16 * 20 + sel4) * 4);   // ldmatrix lane offset (bytes)

    const float* P2; float* Out;
    if (MODE == 0)      { P2 = g_nin2;  Out = g_h1;   }
    else if (MODE == 1) { P2 = g_nin1;  Out = g_h0;   }
    else                { P2 = g_ninL1; Out = g_outs; }

    if (tid < 128) {
        int m = m0 + tid;
        const float* p;
        if (MODE == 0)      p = feats + (long)g_nb1[mp * M1 + m] * D;
        else if (MODE == 1) p = feats + (long)ids[m] * D;
        else                p = g_h0 + ((long)mp * BB + m) * D;
        rowp[tid] = p;
    }
    __syncthreads();

    const float* Wsp = W_self  + ((long)(mp * 2 + l)) * D  * D;
    const float* Wnp = W_neigh + ((long)(mp * 2 + l)) * DE * D;
    const float* P2p = P2 + ((size_t)mp * M + m0) * DE;

    float acc[4][4][4];
    #pragma unroll
    for (int i = 0; i < 4; i++)
        #pragma unroll
        for (int j = 0; j < 4; j++)
            #pragma unroll
            for (int q = 0; q < 4; q++) acc[i][j][q] = 0.f;

    float4 ra0, ra1, rb0, rb1;

#define LDG_H(K0) do {                                                          \
    int _k = (K0);                                                              \
    const float* ap = (_k < D) ? rowp[ar] + _k                                  \
                               : P2p + (long)ar * DE + (_k - D);                \
    ra0 = *(const float4*)(ap + kq);                                            \
    ra1 = *(const float4*)(ap + kq + 4);                                        \
    const float* wrow = (_k < D) ? (Wsp + (long)(_k + bk) * D)                  \
                                 : (Wnp + (long)(_k - D + bk) * D);             \
    rb0 = *(const float4*)(wrow + bn);                                          \
    rb1 = *(const float4*)(wrow + bn + 4);                                      \
} while (0)

#define STS_H(BUF) do {                                                         \
    *(float4*)&As[BUF][ar][kq]     = t4(ra0);                                   \
    *(float4*)&As[BUF][ar][kq + 4] = t4(ra1);                                   \
    *(float4*)&Bs[BUF][bk][bn]     = t4(rb0);                                   \
    *(float4*)&Bs[BUF][bk][bn + 4] = t4(rb1);                                   \
} while (0)

    LDG_H(0);
    STS_H(0);
    __syncthreads();

    for (int it = 0; it < NSTG; ++it) {
        int cur = it & 1;
        if (it + 1 < NSTG) LDG_H((it + 1) * 16);

        uint32_t as_base = sptr(&As[cur][0][0]);
        #pragma unroll
        for (int kk = 0; kk < 16; kk += 8) {
            uint32_t afr[4][4], bfr[4][2];
            #pragma unroll
            for (int mt = 0; mt < 4; mt++) {
                uint32_t ad = as_base + (uint32_t)(((wm * 64 + mt * 16) * 20 + kk) * 4) + lmoff;
                ldsm_x4(afr[mt][0], afr[mt][1], afr[mt][2], afr[mt][3], ad);
            }
            #pragma unroll
            for (int nt = 0; nt < 4; nt++) {
                int cN = wn * 32 + nt * 8 + (lane >> 2);
                bfr[nt][0] = fu(Bs[cur][kk     + (lane & 3)][cN]);
                bfr[nt][1] = fu(Bs[cur][kk + 4 + (lane & 3)][cN]);
            }
            #pragma unroll
            for (int mt = 0; mt < 4; mt++)
                #pragma unroll
                for (int nt = 0; nt < 4; nt++)
                    MMA_TF32(acc[mt][nt], afr[mt], bfr[nt]);
        }

        if (it + 1 < NSTG) { STS_H(cur ^ 1); __syncthreads(); }
    }
#undef LDG_H
#undef STS_H

    // relu in place
    #pragma unroll
    for (int mt = 0; mt < 4; mt++)
        #pragma unroll
        for (int nt = 0; nt < 4; nt++)
            #pragma unroll
            for (int q = 0; q < 4; q++)
                acc[mt][nt][q] = fmaxf(acc[mt][nt][q], 0.f);

    size_t ob = ((size_t)mp * M + m0) * D;
    #pragma unroll
    for (int mt = 0; mt < 4; mt++) {
        int r = wm * 64 + mt * 16 + (lane >> 2);
        #pragma unroll
        for (int nt = 0; nt < 4; nt++) {
            int c = wn * 32 + nt * 8 + 2 * (lane & 3);
            *(float2*)(Out + ob + (size_t)r       * D + c) = make_float2(acc[mt][nt][0], acc[mt][nt][1]);
            *(float2*)(Out + ob + (size_t)(r + 8) * D + c) = make_float2(acc[mt][nt][2], acc[mt][nt][3]);
        }
    }

    if (MODE == 0) {
        // fused 16-row mean -> g_ninL1[:, 0:D]; 16-row groups == mt tiles
        const float inv16 = 1.0f / 16.0f;
        #pragma unroll
        for (int mt = 0; mt < 4; mt++) {
            int b = (m0 + wm * 64 + mt * 16) >> 4;
            float* dst = g_ninL1 + ((size_t)mp * BB + b) * DE;
            #pragma unroll
            for (int nt = 0; nt < 4; nt++) {
                float s0 = acc[mt][nt][0] + acc[mt][nt][2];
                float s1 = acc[mt][nt][1] + acc[mt][nt][3];
                #pragma unroll
                for (int o = 4; o < 32; o <<= 1) {
                    s0 += __shfl_xor_sync(0xffffffffu, s0, o);
                    s1 += __shfl_xor_sync(0xffffffffu, s1, o);
                }
                if (lane < 4) {
                    int c = wn * 32 + nt * 8 + 2 * lane;
                    *(float2*)(dst + c) = make_float2(s0 * inv16, s1 * inv16);
                }
            }
        }
    }
}

// ---------------- edge GEMM (TF32): mean(relu([h0_rep||h1||ee1] @ W_edge)) -> ninL1[:, D:] ----------------
__global__ __launch_bounds__(256) void gemm_edge(const float* __restrict__ edge_emb,
                                                 const float* __restrict__ W_edge,
                                                 int l) {
    constexpr int KTOT = 2 * D + E;       // 288
    constexpr int NSTG = KTOT / 16;       // 18
    int mp = blockIdx.y;
    int m0 = blockIdx.x * 256;

    __shared__ float As[2][256][20];
    __shared__ float Bs[2][16][40];
    __shared__ const float* pH0s[256];
    __shared__ const float* pH1s[256];
    __shared__ const float* pEs[256];

    int tid  = threadIdx.x;
    int lane = tid & 31;
    int w    = tid >> 5;          // warp 0..7, rows 32*w
    int row16 = lane & 15;
    int sel4  = (lane >> 4) * 4;
    uint32_t lmoff = (uint32_t)((row16 * 20 + sel4) * 4);

    {
        int m = m0 + tid;
        pH0s[tid] = g_h0 + ((long)mp * BB + (m >> 4)) * D;
        pH1s[tid] = g_h1 + ((size_t)mp * M1 + m) * D;
        pEs[tid]  = edge_emb + ((long)mp * NEDGE + g_eid1[mp * M1 + m]) * E;
    }
    __syncthreads();

    const float* Wep = W_edge + ((long)(mp * 2 + l)) * KTOT * E;

    float acc[2][4][4];
    #pragma unroll
    for (int i = 0; i < 2; i++)
        #pragma unroll
        for (int j = 0; j < 4; j++)
            #pragma unroll
            for (int q = 0; q < 4; q++) acc[i][j][q] = 0.f;

    float4 ra[4], rb;

#define LDG_E(K0) do {                                                          \
    int _k = (K0);                                                              \
    const float* ap;                                                            \
    if (_k < D)            ap = pH0s[tid] + _k;                                 \
    else if (_k < 2 * D)   ap = pH1s[tid] + (_k - D);                           \
    else                   ap = pEs[tid]  + (_k - 2 * D);                       \
    ra[0] = *(const float4*)(ap);                                               \
    ra[1] = *(const float4*)(ap + 4);                                           \
    ra[2] = *(const float4*)(ap + 8);                                           \
    ra[3] = *(const float4*)(ap + 12);                                          \
    if (tid < 128)                                                              \
        rb = *(const float4*)(Wep + (long)(_k + (tid >> 3)) * E + (tid & 7) * 4);\
} while (0)

#define STS_E(BUF) do {                                                         \
    *(float4*)&As[BUF][tid][0]  = t4(ra[0]);                                    \
    *(float4*)&As[BUF][tid][4]  = t4(ra[1]);                                    \
    *(float4*)&As[BUF][tid][8]  = t4(ra[2]);                                    \
    *(float4*)&As[BUF][tid][12] = t4(ra[3]);                                    \
    if (tid < 128)                                                              \
        *(float4*)&Bs[BUF][tid >> 3][(tid & 7) * 4] = t4(rb);                   \
} while (0)

    LDG_E(0);
    STS_E(0);
    __syncthreads();

    for (int it = 0; it < NSTG; ++it) {
        int cur = it & 1;
        if (it + 1 < NSTG) LDG_E((it + 1) * 16);

        uint32_t as_base = sptr(&As[cur][0][0]);
        #pragma unroll
        for (int kk = 0; kk < 16; kk += 8) {
            uint32_t afr[2][4], bfr[4][2];
            #pragma unroll
            for (int mt = 0; mt < 2; mt++) {
                uint32_t ad = as_base + (uint32_t)(((w * 32 + mt * 16) * 20 + kk) * 4) + lmoff;
                ldsm_x4(afr[mt][0], afr[mt][1], afr[mt][2], afr[mt][3], ad);
            }
            #pragma unroll
            for (int nt = 0; nt < 4; nt++) {
                int cN = nt * 8 + (lane >> 2);
                bfr[nt][0] = fu(Bs[cur][kk     + (lane & 3)][cN]);
                bfr[nt][1] = fu(Bs[cur][kk + 4 + (lane & 3)][cN]);
            }
            #pragma unroll
            for (int mt = 0; mt < 2; mt++)
                #pragma unroll
                for (int nt = 0; nt < 4; nt++)
                    MMA_TF32(acc[mt][nt], afr[mt], bfr[nt]);
        }

        if (it + 1 < NSTG) { STS_E(cur ^ 1); __syncthreads(); }
    }
#undef LDG_E
#undef STS_E

    // relu + fused 16-row mean -> g_ninL1[:, D:DE]; no full e1 store needed
    const float inv16 = 1.0f / 16.0f;
    #pragma unroll
    for (int mt = 0; mt < 2; mt++) {
        int b = (m0 + w * 32 + mt * 16) >> 4;
        float* dst = g_ninL1 + ((size_t)mp * BB + b) * DE + D;
        #pragma unroll
        for (int nt = 0; nt < 4; nt++) {
            float s0 = fmaxf(acc[mt][nt][0], 0.f) + fmaxf(acc[mt][nt][2], 0.f);
            float s1 = fmaxf(acc[mt][nt][1], 0.f) + fmaxf(acc[mt][nt][3], 0.f);
            #pragma unroll
            for (int o = 4; o < 32; o <<= 1) {
                s0 += __shfl_xor_sync(0xffffffffu, s0, o);
                s1 += __shfl_xor_sync(0xffffffffu, s1, o);
            }
            if (lane < 4) {
                int c = nt * 8 + 2 * lane;
                *(float2*)(dst + c) = make_float2(s0 * inv16, s1 * inv16);
            }
        }
    }
}

// ---------------- final fuse: attention + normalize + fc ----------------
__device__ __forceinline__ float blk_red(float v, float* sh) {
    #pragma unroll
    for (int o = 16; o; o >>= 1) v += __shfl_xor_sync(0xffffffffu, v, o);
    int lane = threadIdx.x & 31, wid = threadIdx.x >> 5;
    if (lane == 0) sh[wid] = v;
    __syncthreads();
    float r = sh[0] + sh[1] + sh[2] + sh[3];
    __syncthreads();
    return r;
}

__global__ __launch_bounds__(128) void k_fuse(const float* __restrict__ attn,
                                              const float* __restrict__ fc_w,
                                              const float* __restrict__ fc_b,
                                              float* __restrict__ out) {
    __shared__ float sh[4];
    int b = blockIdx.x, d = threadIdx.x;
    float v0 = g_outs[((size_t)0 * BB + b) * D + d];
    float v1 = g_outs[((size_t)1 * BB + b) * D + d];
    float v2 = g_outs[((size_t)2 * BB + b) * D + d];
    float a  = attn[d];
    float s0 = blk_red(v0 * a, sh);
    float s1 = blk_red(v1 * a, sh);
    float s2 = blk_red(v2 * a, sh);
    s0 = tanhf(s0); s1 = tanhf(s1); s2 = tanhf(s2);
    float mx = fmaxf(s0, fmaxf(s1, s2));
    float e0 = expf(s0 - mx), e1 = expf(s1 - mx), e2 = expf(s2 - mx);
    float inv = 1.f / (e0 + e1 + e2);
    float emb = (e0 * v0 + e1 * v1 + e2 * v2) * inv;
    float n2  = blk_red(emb * emb, sh);
    float nrm = sqrtf(n2);
    emb = emb / fmaxf(nrm, 1e-12f);
    #pragma unroll
    for (int nc = 0; nc < NC; nc++) {
        float r = blk_red(emb * fc_w[d * NC + nc], sh);
        if (d == 0) out[b * NC + nc] = r + fc_b[nc];
    }
}

// ---------------- launch ----------------
extern "C" void kernel_launch(void* const* d_in, const int* in_sizes, int n_in,
                              void* d_out, int out_size) {
    (void)in_sizes; (void)n_in; (void)out_size;
    const int*   ids       = (const int*)  d_in[0];
    const float* feats     = (const float*)d_in[1];
    const float* edge_emb  = (const float*)d_in[2];
    const int*   adj_nodes = (const int*)  d_in[3];
    const int*   adj_edges = (const int*)  d_in[4];
    const float* W_self    = (const float*)d_in[5];
    const float* W_neigh   = (const float*)d_in[6];
    const float* W_edge    = (const float*)d_in[7];
    const float* attn      = (const float*)d_in[8];
    const float* fc_w      = (const float*)d_in[9];
    const float* fc_b      = (const float*)d_in[10];
    float* out = (float*)d_out;

    k_idx<<<(NMP * M1 + 255) / 256, 256>>>(ids, adj_nodes, adj_edges);
    k_mean_hop2<<<NMP * M1 / 8, 256>>>(feats, edge_emb, adj_nodes, adj_edges);
    k_mean_hop1<<<NMP * BB / 8, 256>>>(feats, edge_emb);
    gemm_h<0><<<dim3(M1 / 128, NMP), 256>>>(feats, ids, W_self, W_neigh, 0);
    gemm_h<1><<<dim3(BB / 128, NMP), 256>>>(feats, ids, W_self, W_neigh, 0);
    gemm_edge<<<dim3(M1 / 256, NMP), 256>>>(edge_emb, W_edge, 0);
    gemm_h<2><<<dim3(BB / 128, NMP), 256>>>(feats, ids, W_self, W_neigh, 1);
    k_fuse<<<BB, 128>>>(attn, fc_w, fc_b, out);
}